// round 2
// baseline (speedup 1.0000x reference)
#include <cuda_runtime.h>
#include <math.h>

#define B_ 128
#define U_ 16
#define D_ 256
#define N_ 1024
#define O_ 256
#define KTOT (N_ + D_)   // 1280 unified K for the fused state GEMM

__device__ float g_lr[B_ * U_];

// ---------------------------------------------------------------------------
// Kernel 1: lr[b,u] = softmax_u( dot(X[b,u,:], adaptive_lr[u,:]) / T )
// One block per batch row b; warp w handles unit u=w.
// ---------------------------------------------------------------------------
__global__ __launch_bounds__(512)
void lr_kernel(const float* __restrict__ X,
               const float* __restrict__ alr,
               const float* __restrict__ temperature)
{
    const int b = blockIdx.x;
    const int w = threadIdx.x >> 5;
    const int lane = threadIdx.x & 31;
    const float* xp = X + (size_t)(b * U_ + w) * D_;
    const float* ap = alr + (size_t)w * D_;
    float s = 0.f;
#pragma unroll
    for (int j = 0; j < D_ / 32; ++j)
        s = fmaf(xp[lane + 32 * j], ap[lane + 32 * j], s);
#pragma unroll
    for (int o = 16; o > 0; o >>= 1)
        s += __shfl_down_sync(0xffffffffu, s, o);
    __shared__ float logits[U_];
    if (lane == 0) logits[w] = s;
    __syncthreads();
    if (threadIdx.x == 0) {
        const float invT = 1.f / temperature[0];
        float mx = -1e30f;
        float l[U_];
#pragma unroll
        for (int u = 0; u < U_; ++u) { l[u] = logits[u] * invT; mx = fmaxf(mx, l[u]); }
        float den = 0.f;
        float e[U_];
#pragma unroll
        for (int u = 0; u < U_; ++u) { e[u] = expf(l[u] - mx); den += e[u]; }
        const float inv = 1.f / den;
#pragma unroll
        for (int u = 0; u < U_; ++u) g_lr[b * U_ + u] = e[u] * inv;
    }
}

// ---------------------------------------------------------------------------
// Kernel 2: fused state update (double-buffered smem).
//   pre[b,m]  = sum_{k<1024} state[b,u,k]*W[u,k,m]*sr[u]
//             + sum_{k<256}  X[b,u,k]*Win[u,k,m]  + bias[u,m]
//   new_state = (1-lr)*state + lr*tanh(pre)
// ---------------------------------------------------------------------------
#define BM 128
#define BN 128
#define BK 16
#define TM 8
#define TN 8

__global__ __launch_bounds__(256, 1)
void state_kernel(const float* __restrict__ X, const float* __restrict__ state,
                  const float* __restrict__ W, const float* __restrict__ Win,
                  const float* __restrict__ bias, const float* __restrict__ sr,
                  float* __restrict__ out_state)
{
    const int u = blockIdx.y;
    const int mbase = blockIdx.x * BN;
    const float srv = sr[u];

    __shared__ float As[2][BK][BM];
    __shared__ float Bs[2][BK][BN];

    const int tid = threadIdx.x;
    const int tr = (tid >> 4) * TM;   // batch-row base within tile
    const int tc = (tid & 15) * TN;   // m-col base within tile

    float acc[TM][TN];
#pragma unroll
    for (int i = 0; i < TM; ++i)
#pragma unroll
        for (int j = 0; j < TN; ++j) acc[i][j] = 0.f;

    auto loadA = [&](int kt, int i) -> float4 {
        const int f = tid + i * 256;          // 0..511
        const int arow = f >> 2;              // batch row 0..127
        const int k = kt * BK + (f & 3) * 4;  // global k
        const float* p = (k < N_)
            ? (state + (size_t)(arow * U_ + u) * N_ + k)
            : (X     + (size_t)(arow * U_ + u) * D_ + (k - N_));
        return *reinterpret_cast<const float4*>(p);
    };
    auto loadB = [&](int kt, int i) -> float4 {
        const int f = tid + i * 256;
        const int k = kt * BK + (f >> 5);     // k row within tile
        const int m = mbase + (f & 31) * 4;
        float4 v;
        if (k < N_) {
            v = *reinterpret_cast<const float4*>(W + (size_t)(u * N_ + k) * N_ + m);
            v.x *= srv; v.y *= srv; v.z *= srv; v.w *= srv;
        } else {
            v = *reinterpret_cast<const float4*>(Win + (size_t)(u * D_ + (k - N_)) * N_ + m);
        }
        return v;
    };
    auto storeA = [&](int buf, int i, float4 v) {
        const int f = tid + i * 256;
        const int arow = f >> 2;
        const int k = (f & 3) * 4;
        As[buf][k + 0][arow] = v.x; As[buf][k + 1][arow] = v.y;
        As[buf][k + 2][arow] = v.z; As[buf][k + 3][arow] = v.w;
    };
    auto storeB = [&](int buf, int i, float4 v) {
        const int f = tid + i * 256;
        *reinterpret_cast<float4*>(&Bs[buf][f >> 5][(f & 31) * 4]) = v;
    };

    const int NT = KTOT / BK;  // 80
#pragma unroll
    for (int i = 0; i < 2; ++i) { storeA(0, i, loadA(0, i)); storeB(0, i, loadB(0, i)); }
    __syncthreads();

    float4 aPre[2], bPre[2];
    for (int kt = 0; kt < NT; ++kt) {
        const int cur = kt & 1;
        if (kt + 1 < NT) {
#pragma unroll
            for (int i = 0; i < 2; ++i) { aPre[i] = loadA(kt + 1, i); bPre[i] = loadB(kt + 1, i); }
        }
#pragma unroll
        for (int k = 0; k < BK; ++k) {
            float a[TM], bv[TN];
#pragma unroll
            for (int i = 0; i < TM; ++i) a[i] = As[cur][k][tr + i];
#pragma unroll
            for (int j = 0; j < TN; ++j) bv[j] = Bs[cur][k][tc + j];
#pragma unroll
            for (int i = 0; i < TM; ++i)
#pragma unroll
                for (int j = 0; j < TN; ++j)
                    acc[i][j] = fmaf(a[i], bv[j], acc[i][j]);
        }
        if (kt + 1 < NT) {
            const int nxt = cur ^ 1;
#pragma unroll
            for (int i = 0; i < 2; ++i) { storeA(nxt, i, aPre[i]); storeB(nxt, i, bPre[i]); }
            __syncthreads();
        }
    }

    // Epilogue: bias + tanh + lr blend
#pragma unroll
    for (int i = 0; i < TM; ++i) {
        const int b = tr + i;
        const float lrv = g_lr[b * U_ + u];
        const float* srow = state + (size_t)(b * U_ + u) * N_ + mbase;
        float* orow = out_state + (size_t)(b * U_ + u) * N_ + mbase;
#pragma unroll
        for (int j = 0; j < TN; ++j) {
            const int m = tc + j;
            const float pre = acc[i][j] + bias[u * N_ + mbase + m];
            orow[m] = (1.f - lrv) * srow[m] + lrv * tanhf(pre);
        }
    }
}

// ---------------------------------------------------------------------------
// Kernel 3: output GEMM  out[b,u,o] = sum_n new_state[b,u,n] * Wout[u,n,o]
// 64x64 tiles -> 16*2*4 = 128 CTAs (one wave), double-buffered smem.
// ---------------------------------------------------------------------------
#define CM 64
#define CN 64
#define CK 16

__global__ __launch_bounds__(256, 2)
void out_kernel(const float* __restrict__ ns, const float* __restrict__ Wout,
                float* __restrict__ outy)
{
    const int u = blockIdx.z;
    const int bbase = blockIdx.y * CM;
    const int obase = blockIdx.x * CN;

    __shared__ float As[2][CK][CM];
    __shared__ float Bs[2][CK][CN];

    const int tid = threadIdx.x;
    const int tr = (tid >> 4) * 4;
    const int tc = (tid & 15) * 4;

    float acc[4][4];
#pragma unroll
    for (int i = 0; i < 4; ++i)
#pragma unroll
        for (int j = 0; j < 4; ++j) acc[i][j] = 0.f;

    auto loadA = [&](int kt) -> float4 {
        const int arow = tid >> 2;
        const int k = kt * CK + (tid & 3) * 4;
        return *reinterpret_cast<const float4*>(
            ns + (size_t)((bbase + arow) * U_ + u) * N_ + k);
    };
    auto loadB = [&](int kt) -> float4 {
        const int k = kt * CK + (tid >> 4);
        const int o = obase + (tid & 15) * 4;
        return *reinterpret_cast<const float4*>(Wout + (size_t)(u * N_ + k) * O_ + o);
    };
    auto storeA = [&](int buf, float4 v) {
        const int arow = tid >> 2;
        const int k = (tid & 3) * 4;
        As[buf][k + 0][arow] = v.x; As[buf][k + 1][arow] = v.y;
        As[buf][k + 2][arow] = v.z; As[buf][k + 3][arow] = v.w;
    };
    auto storeB = [&](int buf, float4 v) {
        *reinterpret_cast<float4*>(&Bs[buf][tid >> 4][(tid & 15) * 4]) = v;
    };

    const int NT = N_ / CK;  // 64
    storeA(0, loadA(0)); storeB(0, loadB(0));
    __syncthreads();

    float4 aPre, bPre;
    for (int kt = 0; kt < NT; ++kt) {
        const int cur = kt & 1;
        if (kt + 1 < NT) { aPre = loadA(kt + 1); bPre = loadB(kt + 1); }
#pragma unroll
        for (int k = 0; k < CK; ++k) {
            float a[4], bv[4];
#pragma unroll
            for (int i = 0; i < 4; ++i) a[i] = As[cur][k][tr + i];
#pragma unroll
            for (int j = 0; j < 4; ++j) bv[j] = Bs[cur][k][tc + j];
#pragma unroll
            for (int i = 0; i < 4; ++i)
#pragma unroll
                for (int j = 0; j < 4; ++j)
                    acc[i][j] = fmaf(a[i], bv[j], acc[i][j]);
        }
        if (kt + 1 < NT) {
            storeA(cur ^ 1, aPre); storeB(cur ^ 1, bPre);
            __syncthreads();
        }
    }

#pragma unroll
    for (int i = 0; i < 4; ++i) {
        const int b = bbase + tr + i;
        float* orow = outy + (size_t)(b * U_ + u) * O_ + obase;
#pragma unroll
        for (int j = 0; j < 4; ++j)
            orow[tc + j] = acc[i][j];
    }
}

// ---------------------------------------------------------------------------
extern "C" void kernel_launch(void* const* d_in, const int* in_sizes, int n_in,
                              void* d_out, int out_size)
{
    const float* X    = (const float*)d_in[0];
    const float* st   = (const float*)d_in[1];
    const float* W    = (const float*)d_in[2];
    const float* Win  = (const float*)d_in[3];
    const float* bias = (const float*)d_in[4];
    const float* Wout = (const float*)d_in[5];
    const float* sr   = (const float*)d_in[6];
    const float* alr  = (const float*)d_in[7];
    const float* temp = (const float*)d_in[8];

    float* out_state = (float*)d_out;                          // [B,U,N]
    float* out_y     = out_state + (size_t)B_ * U_ * N_;       // [B,U,O]

    lr_kernel<<<B_, 512>>>(X, alr, temp);
    state_kernel<<<dim3(N_ / BN, U_), 256>>>(X, st, W, Win, bias, sr, out_state);
    out_kernel<<<dim3(O_ / CN, B_ / CM, U_), 256>>>(out_state, Wout, out_y);
}

// round 6
// speedup vs baseline: 1.0443x; 1.0443x over previous
#include <cuda_runtime.h>
#include <math.h>
#include <stdint.h>

#define B_ 128
#define U_ 16
#define D_ 256
#define N_ 1024
#define O_ 256
#define KTOT (N_ + D_)   // 1280 unified K for the fused state GEMM

__device__ float g_lr[B_ * U_];

typedef unsigned long long ull;

__device__ __forceinline__ ull packf2(float a) {
    ull r;
    asm("mov.b64 %0, {%1, %1};" : "=l"(r) : "f"(a));
    return r;
}
__device__ __forceinline__ ull fma2(ull a, ull b, ull c) {
    ull d;
    asm("fma.rn.f32x2 %0, %1, %2, %3;" : "=l"(d) : "l"(a), "l"(b), "l"(c));
    return d;
}
__device__ __forceinline__ void unpackf2(ull v, float& lo, float& hi) {
    asm("mov.b64 {%0, %1}, %2;" : "=f"(lo), "=f"(hi) : "l"(v));
}

// ---------------------------------------------------------------------------
// Kernel 1: lr[b,u] = softmax_u( dot(X[b,u,:], adaptive_lr[u,:]) / T )
// ---------------------------------------------------------------------------
__global__ __launch_bounds__(512)
void lr_kernel(const float* __restrict__ X,
               const float* __restrict__ alr,
               const float* __restrict__ temperature)
{
    const int b = blockIdx.x;
    const int w = threadIdx.x >> 5;
    const int lane = threadIdx.x & 31;
    const float* xp = X + (size_t)(b * U_ + w) * D_;
    const float* ap = alr + (size_t)w * D_;
    float s = 0.f;
#pragma unroll
    for (int j = 0; j < D_ / 32; ++j)
        s = fmaf(xp[lane + 32 * j], ap[lane + 32 * j], s);
#pragma unroll
    for (int o = 16; o > 0; o >>= 1)
        s += __shfl_down_sync(0xffffffffu, s, o);
    __shared__ float logits[U_];
    if (lane == 0) logits[w] = s;
    __syncthreads();
    if (threadIdx.x == 0) {
        const float invT = 1.f / temperature[0];
        float mx = -1e30f, l[U_], e[U_], den = 0.f;
#pragma unroll
        for (int u = 0; u < U_; ++u) { l[u] = logits[u] * invT; mx = fmaxf(mx, l[u]); }
#pragma unroll
        for (int u = 0; u < U_; ++u) { e[u] = expf(l[u] - mx); den += e[u]; }
        const float inv = 1.f / den;
#pragma unroll
        for (int u = 0; u < U_; ++u) g_lr[b * U_ + u] = e[u] * inv;
    }
}

// ---------------------------------------------------------------------------
// Kernel 2: fused state update, FFMA2 inner loop, double-buffered smem.
// ---------------------------------------------------------------------------
#define BM 128
#define BN 128
#define BK 16
#define TM 8
#define TN 8

__global__ __launch_bounds__(256, 1)
void state_kernel(const float* __restrict__ X, const float* __restrict__ state,
                  const float* __restrict__ W, const float* __restrict__ Win,
                  const float* __restrict__ bias, const float* __restrict__ sr,
                  float* __restrict__ out_state)
{
    const int u = blockIdx.y;
    const int mbase = blockIdx.x * BN;
    const float srv = sr[u];

    __shared__ float As[2][BK][BM];
    __shared__ float Bs[2][BK][BN];

    const int tid = threadIdx.x;
    const int tr = (tid >> 4) * TM;
    const int tc = (tid & 15) * TN;

    ull acc2[TM][TN / 2];
#pragma unroll
    for (int i = 0; i < TM; ++i)
#pragma unroll
        for (int j = 0; j < TN / 2; ++j) acc2[i][j] = 0ull;

    auto loadA = [&](int kt, int i) -> float4 {
        const int f = tid + i * 256;
        const int arow = f >> 2;
        const int k = kt * BK + (f & 3) * 4;
        const float* p = (k < N_)
            ? (state + (size_t)(arow * U_ + u) * N_ + k)
            : (X     + (size_t)(arow * U_ + u) * D_ + (k - N_));
        return *reinterpret_cast<const float4*>(p);
    };
    auto loadB = [&](int kt, int i) -> float4 {
        const int f = tid + i * 256;
        const int k = kt * BK + (f >> 5);
        const int m = mbase + (f & 31) * 4;
        float4 v;
        if (k < N_) {
            v = *reinterpret_cast<const float4*>(W + (size_t)(u * N_ + k) * N_ + m);
            v.x *= srv; v.y *= srv; v.z *= srv; v.w *= srv;
        } else {
            v = *reinterpret_cast<const float4*>(Win + (size_t)(u * D_ + (k - N_)) * N_ + m);
        }
        return v;
    };
    auto storeA = [&](int buf, int i, float4 v) {
        const int f = tid + i * 256;
        const int arow = f >> 2;
        const int k = (f & 3) * 4;
        As[buf][k + 0][arow] = v.x; As[buf][k + 1][arow] = v.y;
        As[buf][k + 2][arow] = v.z; As[buf][k + 3][arow] = v.w;
    };
    auto storeB = [&](int buf, int i, float4 v) {
        const int f = tid + i * 256;
        *reinterpret_cast<float4*>(&Bs[buf][f >> 5][(f & 31) * 4]) = v;
    };

    const int NT = KTOT / BK;  // 80
#pragma unroll
    for (int i = 0; i < 2; ++i) { storeA(0, i, loadA(0, i)); storeB(0, i, loadB(0, i)); }
    __syncthreads();

    float4 aPre[2], bPre[2];
    for (int kt = 0; kt < NT; ++kt) {
        const int cur = kt & 1;
        if (kt + 1 < NT) {
#pragma unroll
            for (int i = 0; i < 2; ++i) { aPre[i] = loadA(kt + 1, i); bPre[i] = loadB(kt + 1, i); }
        }
#pragma unroll
        for (int k = 0; k < BK; ++k) {
            ull ap[TM], bp[TN / 2];
#pragma unroll
            for (int i = 0; i < TM; ++i) ap[i] = packf2(As[cur][k][tr + i]);
#pragma unroll
            for (int j = 0; j < TN / 2; ++j)
                bp[j] = *reinterpret_cast<const ull*>(&Bs[cur][k][tc + 2 * j]);
#pragma unroll
            for (int i = 0; i < TM; ++i)
#pragma unroll
                for (int j = 0; j < TN / 2; ++j)
                    acc2[i][j] = fma2(ap[i], bp[j], acc2[i][j]);
        }
        if (kt + 1 < NT) {
            const int nxt = cur ^ 1;
#pragma unroll
            for (int i = 0; i < 2; ++i) { storeA(nxt, i, aPre[i]); storeB(nxt, i, bPre[i]); }
            __syncthreads();
        }
    }

    // Epilogue: bias + tanh + lr blend
#pragma unroll
    for (int i = 0; i < TM; ++i) {
        const int b = tr + i;
        const float lrv = g_lr[b * U_ + u];
        const float* srow = state + (size_t)(b * U_ + u) * N_ + mbase;
        float* orow = out_state + (size_t)(b * U_ + u) * N_ + mbase;
#pragma unroll
        for (int j = 0; j < TN / 2; ++j) {
            float v0, v1;
            unpackf2(acc2[i][j], v0, v1);
            const int m0 = tc + 2 * j;
            const float pre0 = v0 + bias[u * N_ + mbase + m0];
            const float pre1 = v1 + bias[u * N_ + mbase + m0 + 1];
            float2 o;
            o.x = (1.f - lrv) * srow[m0] + lrv * tanhf(pre0);
            o.y = (1.f - lrv) * srow[m0 + 1] + lrv * tanhf(pre1);
            *reinterpret_cast<float2*>(orow + m0) = o;
        }
    }
}

// ---------------------------------------------------------------------------
// Kernel 3: output GEMM, FFMA2 inner loop, 64x64 tiles -> 128 CTAs.
// ---------------------------------------------------------------------------
#define CM 64
#define CN 64
#define CK 16

__global__ __launch_bounds__(256, 2)
void out_kernel(const float* __restrict__ ns, const float* __restrict__ Wout,
                float* __restrict__ outy)
{
    const int u = blockIdx.z;
    const int bbase = blockIdx.y * CM;
    const int obase = blockIdx.x * CN;

    __shared__ float As[2][CK][CM];
    __shared__ float Bs[2][CK][CN];

    const int tid = threadIdx.x;
    const int tr = (tid >> 4) * 4;
    const int tc = (tid & 15) * 4;

    ull acc2[4][2];
#pragma unroll
    for (int i = 0; i < 4; ++i) { acc2[i][0] = 0ull; acc2[i][1] = 0ull; }

    auto loadA = [&](int kt) -> float4 {
        const int arow = tid >> 2;
        const int k = kt * CK + (tid & 3) * 4;
        return *reinterpret_cast<const float4*>(
            ns + (size_t)((bbase + arow) * U_ + u) * N_ + k);
    };
    auto loadB = [&](int kt) -> float4 {
        const int k = kt * CK + (tid >> 4);
        const int o = obase + (tid & 15) * 4;
        return *reinterpret_cast<const float4*>(Wout + (size_t)(u * N_ + k) * O_ + o);
    };
    auto storeA = [&](int buf, float4 v) {
        const int arow = tid >> 2;
        const int k = (tid & 3) * 4;
        As[buf][k + 0][arow] = v.x; As[buf][k + 1][arow] = v.y;
        As[buf][k + 2][arow] = v.z; As[buf][k + 3][arow] = v.w;
    };
    auto storeB = [&](int buf, float4 v) {
        *reinterpret_cast<float4*>(&Bs[buf][tid >> 4][(tid & 15) * 4]) = v;
    };

    const int NT = N_ / CK;  // 64
    storeA(0, loadA(0)); storeB(0, loadB(0));
    __syncthreads();

    float4 aPre, bPre;
    for (int kt = 0; kt < NT; ++kt) {
        const int cur = kt & 1;
        if (kt + 1 < NT) { aPre = loadA(kt + 1); bPre = loadB(kt + 1); }
#pragma unroll
        for (int k = 0; k < CK; ++k) {
            ull ap[4], bp[2];
#pragma unroll
            for (int i = 0; i < 4; ++i) ap[i] = packf2(As[cur][k][tr + i]);
            bp[0] = *reinterpret_cast<const ull*>(&Bs[cur][k][tc]);
            bp[1] = *reinterpret_cast<const ull*>(&Bs[cur][k][tc + 2]);
#pragma unroll
            for (int i = 0; i < 4; ++i) {
                acc2[i][0] = fma2(ap[i], bp[0], acc2[i][0]);
                acc2[i][1] = fma2(ap[i], bp[1], acc2[i][1]);
            }
        }
        if (kt + 1 < NT) {
            storeA(cur ^ 1, aPre); storeB(cur ^ 1, bPre);
            __syncthreads();
        }
    }

#pragma unroll
    for (int i = 0; i < 4; ++i) {
        const int b = bbase + tr + i;
        float* orow = outy + (size_t)(b * U_ + u) * O_ + obase;
        float4 o;
        unpackf2(acc2[i][0], o.x, o.y);
        unpackf2(acc2[i][1], o.z, o.w);
        *reinterpret_cast<float4*>(orow + tc) = o;
    }
}

// ---------------------------------------------------------------------------
extern "C" void kernel_launch(void* const* d_in, const int* in_sizes, int n_in,
                              void* d_out, int out_size)
{
    const float* X    = (const float*)d_in[0];
    const float* st   = (const float*)d_in[1];
    const float* W    = (const float*)d_in[2];
    const float* Win  = (const float*)d_in[3];
    const float* bias = (const float*)d_in[4];
    const float* Wout = (const float*)d_in[5];
    const float* sr   = (const float*)d_in[6];
    const float* alr  = (const float*)d_in[7];
    const float* temp = (const float*)d_in[8];

    float* out_state = (float*)d_out;                          // [B,U,N]
    float* out_y     = out_state + (size_t)B_ * U_ * N_;       // [B,U,O]

    lr_kernel<<<B_, 512>>>(X, alr, temp);
    state_kernel<<<dim3(N_ / BN, U_), 256>>>(X, st, W, Win, bias, sr, out_state);
    out_kernel<<<dim3(O_ / CN, B_ / CM, U_), 256>>>(out_state, Wout, out_y);
}

// round 7
// speedup vs baseline: 1.2873x; 1.2327x over previous
#include <cuda_runtime.h>
#include <cuda_bf16.h>
#include <math.h>
#include <stdint.h>

#define B_ 128
#define U_ 16
#define D_ 256
#define N_ 1024
#define O_ 256

__device__ float g_lr[B_ * U_];

// ---------------------------------------------------------------------------
// helpers
// ---------------------------------------------------------------------------
__device__ __forceinline__ uint32_t smem_u32(const void* p) {
    uint32_t a;
    asm("{ .reg .u64 t; cvta.to.shared.u64 t, %1; cvt.u32.u64 %0, t; }" : "=r"(a) : "l"(p));
    return a;
}
__device__ __forceinline__ void ldsm_x4(uint32_t* r, uint32_t a) {
    asm volatile("ldmatrix.sync.aligned.m8n8.x4.shared.b16 {%0,%1,%2,%3}, [%4];"
        : "=r"(r[0]), "=r"(r[1]), "=r"(r[2]), "=r"(r[3]) : "r"(a));
}
__device__ __forceinline__ void ldsm_x2t(uint32_t* r, uint32_t a) {
    asm volatile("ldmatrix.sync.aligned.m8n8.x2.trans.shared.b16 {%0,%1}, [%2];"
        : "=r"(r[0]), "=r"(r[1]) : "r"(a));
}
__device__ __forceinline__ void mma_bf16(float* d, const uint32_t* a, const uint32_t* b) {
    asm volatile("mma.sync.aligned.m16n8k16.row.col.f32.bf16.bf16.f32 "
        "{%0,%1,%2,%3}, {%4,%5,%6,%7}, {%8,%9}, {%0,%1,%2,%3};"
        : "+f"(d[0]), "+f"(d[1]), "+f"(d[2]), "+f"(d[3])
        : "r"(a[0]), "r"(a[1]), "r"(a[2]), "r"(a[3]), "r"(b[0]), "r"(b[1]));
}
// hi/lo bf16 split of 4 floats; packed bf16 pairs in element order
__device__ __forceinline__ void split4(float4 v, uint2& hi, uint2& lo) {
    __nv_bfloat16 h0 = __float2bfloat16(v.x), h1 = __float2bfloat16(v.y);
    __nv_bfloat16 h2 = __float2bfloat16(v.z), h3 = __float2bfloat16(v.w);
    __nv_bfloat16 l0 = __float2bfloat16(v.x - __bfloat162float(h0));
    __nv_bfloat16 l1 = __float2bfloat16(v.y - __bfloat162float(h1));
    __nv_bfloat16 l2 = __float2bfloat16(v.z - __bfloat162float(h2));
    __nv_bfloat16 l3 = __float2bfloat16(v.w - __bfloat162float(h3));
    hi.x = (uint32_t)__bfloat16_as_ushort(h0) | ((uint32_t)__bfloat16_as_ushort(h1) << 16);
    hi.y = (uint32_t)__bfloat16_as_ushort(h2) | ((uint32_t)__bfloat16_as_ushort(h3) << 16);
    lo.x = (uint32_t)__bfloat16_as_ushort(l0) | ((uint32_t)__bfloat16_as_ushort(l1) << 16);
    lo.y = (uint32_t)__bfloat16_as_ushort(l2) | ((uint32_t)__bfloat16_as_ushort(l3) << 16);
}

// ---------------------------------------------------------------------------
// Kernel 1: lr softmax (unchanged)
// ---------------------------------------------------------------------------
__global__ __launch_bounds__(512)
void lr_kernel(const float* __restrict__ X, const float* __restrict__ alr,
               const float* __restrict__ temperature)
{
    const int b = blockIdx.x;
    const int w = threadIdx.x >> 5;
    const int lane = threadIdx.x & 31;
    const float* xp = X + (size_t)(b * U_ + w) * D_;
    const float* ap = alr + (size_t)w * D_;
    float s = 0.f;
#pragma unroll
    for (int j = 0; j < D_ / 32; ++j)
        s = fmaf(xp[lane + 32 * j], ap[lane + 32 * j], s);
#pragma unroll
    for (int o = 16; o > 0; o >>= 1)
        s += __shfl_down_sync(0xffffffffu, s, o);
    __shared__ float logits[U_];
    if (lane == 0) logits[w] = s;
    __syncthreads();
    if (threadIdx.x == 0) {
        const float invT = 1.f / temperature[0];
        float mx = -1e30f, l[U_], e[U_], den = 0.f;
#pragma unroll
        for (int u = 0; u < U_; ++u) { l[u] = logits[u] * invT; mx = fmaxf(mx, l[u]); }
#pragma unroll
        for (int u = 0; u < U_; ++u) { e[u] = expf(l[u] - mx); den += e[u]; }
        const float inv = 1.f / den;
#pragma unroll
        for (int u = 0; u < U_; ++u) g_lr[b * U_ + u] = e[u] * inv;
    }
}

// ---------------------------------------------------------------------------
// Kernel 2: state GEMM via mma.sync bf16 (hi/lo split, 3 passes).
// CTA 128(batch) x 128(n), 8 warps (2m x 4n), warp tile 64x32.
// K = 1280 in 80 chunks of 16. Double-buffered smem, 1 sync/chunk.
// ---------------------------------------------------------------------------
#define APITCH 48           // bytes per A smem row (16 bf16 + 8 pad)
#define ASZ (128 * APITCH)  // 6144
#define SBPITCH 272         // 128 bf16 + 8 pad
#define SBSZ (16 * SBPITCH) // 4352

__global__ __launch_bounds__(256, 1)
void state_kernel(const float* __restrict__ X, const float* __restrict__ state,
                  const float* __restrict__ W, const float* __restrict__ Win,
                  const float* __restrict__ bias, const float* __restrict__ sr,
                  float* __restrict__ out_state)
{
    __shared__ __align__(16) char sm[2 * 2 * ASZ + 2 * 2 * SBSZ];  // 41984 B
    const int tid = threadIdx.x, wid = tid >> 5, lane = tid & 31;
    const int u = blockIdx.y;
    const int mbase = blockIdx.x * 128;
    const float srv = sr[u];

    auto Aoff = [](int buf, int part) { return (buf * 2 + part) * ASZ; };
    auto Boff = [](int buf, int part) { return 2 * 2 * ASZ + (buf * 2 + part) * SBSZ; };

    auto ldA = [&](int kt, int i) -> float4 {
        const int f = tid + i * 256;
        const int row = f >> 2;
        const int kg = kt * 16 + (f & 3) * 4;
        const float* p = (kg < N_)
            ? (state + ((size_t)row * U_ + u) * N_ + kg)
            : (X     + ((size_t)row * U_ + u) * D_ + (kg - N_));
        return *(const float4*)p;
    };
    auto ldB = [&](int kt, int i) -> float4 {
        const int f = tid + i * 256;
        const int kg = kt * 16 + (f >> 5);
        const int n4 = (f & 31) * 4;
        float4 v;
        if (kg < N_) {
            v = *(const float4*)(W + ((size_t)u * N_ + kg) * N_ + mbase + n4);
            v.x *= srv; v.y *= srv; v.z *= srv; v.w *= srv;
        } else {
            v = *(const float4*)(Win + ((size_t)u * D_ + (kg - N_)) * N_ + mbase + n4);
        }
        return v;
    };
    auto stA = [&](int buf, int i, float4 v) {
        const int f = tid + i * 256;
        const int row = f >> 2;
        const int kb = (f & 3) * 8;           // byte offset within row
        uint2 hi, lo; split4(v, hi, lo);
        *(uint2*)(sm + Aoff(buf, 0) + row * APITCH + kb) = hi;
        *(uint2*)(sm + Aoff(buf, 1) + row * APITCH + kb) = lo;
    };
    auto stB = [&](int buf, int i, float4 v) {
        const int f = tid + i * 256;
        const int k = f >> 5;
        const int nb = (f & 31) * 8;
        uint2 hi, lo; split4(v, hi, lo);
        *(uint2*)(sm + Boff(buf, 0) + k * SBPITCH + nb) = hi;
        *(uint2*)(sm + Boff(buf, 1) + k * SBPITCH + nb) = lo;
    };

    const uint32_t smb = smem_u32(sm);
    const int wm = wid >> 2, wn = wid & 3;
    const int amat = lane >> 3, arin = lane & 7;
    const uint32_t a_lane = (uint32_t)(((amat & 1) * 8 + arin) * APITCH + (amat >> 1) * 16);
    const uint32_t b_lane = (uint32_t)((lane & 15) * SBPITCH);

    float acc[4][4][4];
#pragma unroll
    for (int t = 0; t < 4; ++t)
#pragma unroll
        for (int j = 0; j < 4; ++j)
#pragma unroll
            for (int r = 0; r < 4; ++r) acc[t][j][r] = 0.f;

    // preload chunk 0
    {
        float4 a0 = ldA(0, 0), a1 = ldA(0, 1), b0 = ldB(0, 0), b1 = ldB(0, 1);
        stA(0, 0, a0); stA(0, 1, a1); stB(0, 0, b0); stB(0, 1, b1);
    }
    __syncthreads();

    const int NT = 80;
    float4 aPre0, aPre1, bPre0, bPre1;
    for (int kt = 0; kt < NT; ++kt) {
        const int cur = kt & 1;
        if (kt + 1 < NT) {
            aPre0 = ldA(kt + 1, 0); aPre1 = ldA(kt + 1, 1);
            bPre0 = ldB(kt + 1, 0); bPre1 = ldB(kt + 1, 1);
        }
        uint32_t ah[4][4], al[4][4], bh[4][2], bl[4][2];
        const uint32_t Ah = smb + Aoff(cur, 0) + a_lane + wm * 64 * APITCH;
        const uint32_t Al = smb + Aoff(cur, 1) + a_lane + wm * 64 * APITCH;
#pragma unroll
        for (int t = 0; t < 4; ++t) {
            ldsm_x4(ah[t], Ah + t * 16 * APITCH);
            ldsm_x4(al[t], Al + t * 16 * APITCH);
        }
        const uint32_t Bh = smb + Boff(cur, 0) + b_lane + wn * 64;  // 32 cols * 2B
        const uint32_t Bl = smb + Boff(cur, 1) + b_lane + wn * 64;
#pragma unroll
        for (int j = 0; j < 4; ++j) {
            ldsm_x2t(bh[j], Bh + j * 16);
            ldsm_x2t(bl[j], Bl + j * 16);
        }
#pragma unroll
        for (int t = 0; t < 4; ++t)
#pragma unroll
            for (int j = 0; j < 4; ++j) {
                mma_bf16(acc[t][j], ah[t], bh[j]);
                mma_bf16(acc[t][j], ah[t], bl[j]);
                mma_bf16(acc[t][j], al[t], bh[j]);
            }
        if (kt + 1 < NT) {
            const int nxt = cur ^ 1;
            stA(nxt, 0, aPre0); stA(nxt, 1, aPre1);
            stB(nxt, 0, bPre0); stB(nxt, 1, bPre1);
        }
        __syncthreads();
    }

    // epilogue: bias + tanh + lr blend
    const int g = lane >> 2, tig = lane & 3;
#pragma unroll
    for (int t = 0; t < 4; ++t) {
#pragma unroll
        for (int half = 0; half < 2; ++half) {
            const int b = wm * 64 + t * 16 + g + half * 8;
            const float lrv = g_lr[b * U_ + u];
            const float* srow = state + ((size_t)b * U_ + u) * N_;
            float* orow = out_state + ((size_t)b * U_ + u) * N_;
#pragma unroll
            for (int j = 0; j < 4; ++j) {
                const int c = mbase + wn * 32 + j * 8 + tig * 2;
                const float p0 = acc[t][j][half * 2 + 0] + bias[u * N_ + c];
                const float p1 = acc[t][j][half * 2 + 1] + bias[u * N_ + c + 1];
                float2 o;
                o.x = (1.f - lrv) * srow[c]     + lrv * tanhf(p0);
                o.y = (1.f - lrv) * srow[c + 1] + lrv * tanhf(p1);
                *(float2*)(orow + c) = o;
            }
        }
    }
}

// ---------------------------------------------------------------------------
// Kernel 3: out GEMM via mma.sync bf16. CTA 128(batch) x 64(o),
// 8 warps (4m x 2n), warp tile 32x32. K=1024 in 64 chunks.
// ---------------------------------------------------------------------------
#define OBPITCH 144          // 64 bf16 + 8 pad
#define OBSZ (16 * OBPITCH)  // 2304

__global__ __launch_bounds__(256, 1)
void out_kernel(const float* __restrict__ ns, const float* __restrict__ Wout,
                float* __restrict__ outy)
{
    __shared__ __align__(16) char sm[2 * 2 * ASZ + 2 * 2 * OBSZ];  // 33792 B
    const int tid = threadIdx.x, wid = tid >> 5, lane = tid & 31;
    const int u = blockIdx.y;
    const int obase = blockIdx.x * 64;

    auto Aoff = [](int buf, int part) { return (buf * 2 + part) * ASZ; };
    auto Boff = [](int buf, int part) { return 2 * 2 * ASZ + (buf * 2 + part) * OBSZ; };

    auto ldA = [&](int kt, int i) -> float4 {
        const int f = tid + i * 256;
        const int row = f >> 2;
        const int kg = kt * 16 + (f & 3) * 4;
        return *(const float4*)(ns + ((size_t)row * U_ + u) * N_ + kg);
    };
    auto ldB = [&](int kt) -> float4 {   // 256 float4 total -> 1 per thread
        const int k = tid >> 4;
        const int n4 = (tid & 15) * 4;
        return *(const float4*)(Wout + ((size_t)u * N_ + kt * 16 + k) * O_ + obase + n4);
    };
    auto stA = [&](int buf, int i, float4 v) {
        const int f = tid + i * 256;
        const int row = f >> 2;
        const int kb = (f & 3) * 8;
        uint2 hi, lo; split4(v, hi, lo);
        *(uint2*)(sm + Aoff(buf, 0) + row * APITCH + kb) = hi;
        *(uint2*)(sm + Aoff(buf, 1) + row * APITCH + kb) = lo;
    };
    auto stB = [&](int buf, float4 v) {
        const int k = tid >> 4;
        const int nb = (tid & 15) * 8;
        uint2 hi, lo; split4(v, hi, lo);
        *(uint2*)(sm + Boff(buf, 0) + k * OBPITCH + nb) = hi;
        *(uint2*)(sm + Boff(buf, 1) + k * OBPITCH + nb) = lo;
    };

    const uint32_t smb = smem_u32(sm);
    const int wm = wid >> 1, wn = wid & 1;
    const int amat = lane >> 3, arin = lane & 7;
    const uint32_t a_lane = (uint32_t)(((amat & 1) * 8 + arin) * APITCH + (amat >> 1) * 16);
    const uint32_t b_lane = (uint32_t)((lane & 15) * OBPITCH);

    float acc[2][4][4];
#pragma unroll
    for (int t = 0; t < 2; ++t)
#pragma unroll
        for (int j = 0; j < 4; ++j)
#pragma unroll
            for (int r = 0; r < 4; ++r) acc[t][j][r] = 0.f;

    {
        float4 a0 = ldA(0, 0), a1 = ldA(0, 1), b0 = ldB(0);
        stA(0, 0, a0); stA(0, 1, a1); stB(0, b0);
    }
    __syncthreads();

    const int NT = 64;
    float4 aPre0, aPre1, bPre0;
    for (int kt = 0; kt < NT; ++kt) {
        const int cur = kt & 1;
        if (kt + 1 < NT) {
            aPre0 = ldA(kt + 1, 0); aPre1 = ldA(kt + 1, 1); bPre0 = ldB(kt + 1);
        }
        uint32_t ah[2][4], al[2][4], bh[4][2], bl[4][2];
        const uint32_t Ah = smb + Aoff(cur, 0) + a_lane + wm * 32 * APITCH;
        const uint32_t Al = smb + Aoff(cur, 1) + a_lane + wm * 32 * APITCH;
#pragma unroll
        for (int t = 0; t < 2; ++t) {
            ldsm_x4(ah[t], Ah + t * 16 * APITCH);
            ldsm_x4(al[t], Al + t * 16 * APITCH);
        }
        const uint32_t Bh = smb + Boff(cur, 0) + b_lane + wn * 64;
        const uint32_t Bl = smb + Boff(cur, 1) + b_lane + wn * 64;
#pragma unroll
        for (int j = 0; j < 4; ++j) {
            ldsm_x2t(bh[j], Bh + j * 16);
            ldsm_x2t(bl[j], Bl + j * 16);
        }
#pragma unroll
        for (int t = 0; t < 2; ++t)
#pragma unroll
            for (int j = 0; j < 4; ++j) {
                mma_bf16(acc[t][j], ah[t], bh[j]);
                mma_bf16(acc[t][j], ah[t], bl[j]);
                mma_bf16(acc[t][j], al[t], bh[j]);
            }
        if (kt + 1 < NT) {
            const int nxt = cur ^ 1;
            stA(nxt, 0, aPre0); stA(nxt, 1, aPre1); stB(nxt, bPre0);
        }
        __syncthreads();
    }

    const int g = lane >> 2, tig = lane & 3;
#pragma unroll
    for (int t = 0; t < 2; ++t) {
#pragma unroll
        for (int half = 0; half < 2; ++half) {
            const int b = wm * 32 + t * 16 + g + half * 8;
            float* orow = outy + ((size_t)b * U_ + u) * O_;
#pragma unroll
            for (int j = 0; j < 4; ++j) {
                const int c = obase + wn * 32 + j * 8 + tig * 2;
                float2 o;
                o.x = acc[t][j][half * 2 + 0];
                o.y = acc[t][j][half * 2 + 1];
                *(float2*)(orow + c) = o;
            }
        }
    }
}

// ---------------------------------------------------------------------------
extern "C" void kernel_launch(void* const* d_in, const int* in_sizes, int n_in,
                              void* d_out, int out_size)
{
    const float* X    = (const float*)d_in[0];
    const float* st   = (const float*)d_in[1];
    const float* W    = (const float*)d_in[2];
    const float* Win  = (const float*)d_in[3];
    const float* bias = (const float*)d_in[4];
    const float* Wout = (const float*)d_in[5];
    const float* sr   = (const float*)d_in[6];
    const float* alr  = (const float*)d_in[7];
    const float* temp = (const float*)d_in[8];

    float* out_state = (float*)d_out;                     // [B,U,N]
    float* out_y     = out_state + (size_t)B_ * U_ * N_;  // [B,U,O]

    lr_kernel<<<B_, 512>>>(X, alr, temp);
    state_kernel<<<dim3(N_ / 128, U_), 256>>>(X, st, W, Win, bias, sr, out_state);
    out_kernel<<<dim3(O_ / 64, U_), 256>>>(out_state, Wout, out_y);
}

// round 9
// speedup vs baseline: 1.3151x; 1.0216x over previous
#include <cuda_runtime.h>
#include <cuda_bf16.h>
#include <math.h>
#include <stdint.h>

#define B_ 128
#define U_ 16
#define D_ 256
#define N_ 1024
#define O_ 256
#define KTOT (N_ + D_)   // 1280 unified K

__device__ float g_lr[B_ * U_];
// bf16 hi/lo scratch (prepass outputs)
__device__ __nv_bfloat16 g_Bhi[U_ * KTOT * N_];   // [u][k][n]  (W*sr ; Win)
__device__ __nv_bfloat16 g_Blo[U_ * KTOT * N_];
__device__ __nv_bfloat16 g_Ahi[B_ * U_ * KTOT];   // [b][u][k]  (state | X)
__device__ __nv_bfloat16 g_Alo[B_ * U_ * KTOT];
__device__ __nv_bfloat16 g_Ohi[U_ * N_ * O_];     // [u][k][o]  Wout
__device__ __nv_bfloat16 g_Olo[U_ * N_ * O_];
__device__ __nv_bfloat16 g_NShi[B_ * U_ * N_];    // [b][u][n]  new_state
__device__ __nv_bfloat16 g_NSlo[B_ * U_ * N_];

// ---------------------------------------------------------------------------
// helpers
// ---------------------------------------------------------------------------
__device__ __forceinline__ uint32_t smem_u32(const void* p) {
    uint32_t a;
    asm("{ .reg .u64 t; cvta.to.shared.u64 t, %1; cvt.u32.u64 %0, t; }" : "=r"(a) : "l"(p));
    return a;
}
__device__ __forceinline__ void ldsm_x4(uint32_t* r, uint32_t a) {
    asm volatile("ldmatrix.sync.aligned.m8n8.x4.shared.b16 {%0,%1,%2,%3}, [%4];"
        : "=r"(r[0]), "=r"(r[1]), "=r"(r[2]), "=r"(r[3]) : "r"(a));
}
__device__ __forceinline__ void ldsm_x2t(uint32_t* r, uint32_t a) {
    asm volatile("ldmatrix.sync.aligned.m8n8.x2.trans.shared.b16 {%0,%1}, [%2];"
        : "=r"(r[0]), "=r"(r[1]) : "r"(a));
}
__device__ __forceinline__ void mma_bf16(float* d, const uint32_t* a, const uint32_t* b) {
    asm volatile("mma.sync.aligned.m16n8k16.row.col.f32.bf16.bf16.f32 "
        "{%0,%1,%2,%3}, {%4,%5,%6,%7}, {%8,%9}, {%0,%1,%2,%3};"
        : "+f"(d[0]), "+f"(d[1]), "+f"(d[2]), "+f"(d[3])
        : "r"(a[0]), "r"(a[1]), "r"(a[2]), "r"(a[3]), "r"(b[0]), "r"(b[1]));
}
__device__ __forceinline__ void split4(float4 v, uint2& hi, uint2& lo) {
    __nv_bfloat16 h0 = __float2bfloat16(v.x), h1 = __float2bfloat16(v.y);
    __nv_bfloat16 h2 = __float2bfloat16(v.z), h3 = __float2bfloat16(v.w);
    __nv_bfloat16 l0 = __float2bfloat16(v.x - __bfloat162float(h0));
    __nv_bfloat16 l1 = __float2bfloat16(v.y - __bfloat162float(h1));
    __nv_bfloat16 l2 = __float2bfloat16(v.z - __bfloat162float(h2));
    __nv_bfloat16 l3 = __float2bfloat16(v.w - __bfloat162float(h3));
    hi.x = (uint32_t)__bfloat16_as_ushort(h0) | ((uint32_t)__bfloat16_as_ushort(h1) << 16);
    hi.y = (uint32_t)__bfloat16_as_ushort(h2) | ((uint32_t)__bfloat16_as_ushort(h3) << 16);
    lo.x = (uint32_t)__bfloat16_as_ushort(l0) | ((uint32_t)__bfloat16_as_ushort(l1) << 16);
    lo.y = (uint32_t)__bfloat16_as_ushort(l2) | ((uint32_t)__bfloat16_as_ushort(l3) << 16);
}

// ---------------------------------------------------------------------------
// Kernel 1: lr softmax
// ---------------------------------------------------------------------------
__global__ __launch_bounds__(512)
void lr_kernel(const float* __restrict__ X, const float* __restrict__ alr,
               const float* __restrict__ temperature)
{
    const int b = blockIdx.x;
    const int w = threadIdx.x >> 5;
    const int lane = threadIdx.x & 31;
    const float* xp = X + (size_t)(b * U_ + w) * D_;
    const float* ap = alr + (size_t)w * D_;
    float s = 0.f;
#pragma unroll
    for (int j = 0; j < D_ / 32; ++j)
        s = fmaf(xp[lane + 32 * j], ap[lane + 32 * j], s);
#pragma unroll
    for (int o = 16; o > 0; o >>= 1)
        s += __shfl_down_sync(0xffffffffu, s, o);
    __shared__ float logits[U_];
    if (lane == 0) logits[w] = s;
    __syncthreads();
    if (threadIdx.x == 0) {
        const float invT = 1.f / temperature[0];
        float mx = -1e30f, l[U_], e[U_], den = 0.f;
#pragma unroll
        for (int u = 0; u < U_; ++u) { l[u] = logits[u] * invT; mx = fmaxf(mx, l[u]); }
#pragma unroll
        for (int u = 0; u < U_; ++u) { e[u] = expf(l[u] - mx); den += e[u]; }
        const float inv = 1.f / den;
#pragma unroll
        for (int u = 0; u < U_; ++u) g_lr[b * U_ + u] = e[u] * inv;
    }
}

// ---------------------------------------------------------------------------
// Prepass conversions (streaming, memory-bound)
// ---------------------------------------------------------------------------
__global__ __launch_bounds__(256)
void convB_kernel(const float* __restrict__ W, const float* __restrict__ Win,
                  const float* __restrict__ sr)
{
    const int q = blockIdx.x * 256 + threadIdx.x;  // quad id, total 16*1280*256
    const int n4 = (q & 255) * 4;
    const int kk = (q >> 8) % KTOT;
    const int u  = q / (256 * KTOT);
    float4 v;
    if (kk < N_) {
        v = *(const float4*)(W + ((size_t)u * N_ + kk) * N_ + n4);
        const float s = sr[u];
        v.x *= s; v.y *= s; v.z *= s; v.w *= s;
    } else {
        v = *(const float4*)(Win + ((size_t)u * D_ + (kk - N_)) * N_ + n4);
    }
    uint2 hi, lo; split4(v, hi, lo);
    const size_t o = ((size_t)u * KTOT + kk) * N_ + n4;
    *(uint2*)(g_Bhi + o) = hi;
    *(uint2*)(g_Blo + o) = lo;
}

__global__ __launch_bounds__(256)
void convA_kernel(const float* __restrict__ X, const float* __restrict__ state)
{
    const int q = blockIdx.x * 256 + threadIdx.x;  // total 128*16*320
    const int k4 = (q % 320) * 4;
    const int u  = (q / 320) & 15;
    const int b  = q / (320 * 16);
    float4 v = (k4 < N_)
        ? *(const float4*)(state + ((size_t)b * U_ + u) * N_ + k4)
        : *(const float4*)(X + ((size_t)b * U_ + u) * D_ + (k4 - N_));
    uint2 hi, lo; split4(v, hi, lo);
    const size_t o = ((size_t)b * U_ + u) * KTOT + k4;
    *(uint2*)(g_Ahi + o) = hi;
    *(uint2*)(g_Alo + o) = lo;
}

__global__ __launch_bounds__(256)
void convO_kernel(const float* __restrict__ Wout)
{
    const int q = blockIdx.x * 256 + threadIdx.x;  // total 16*1024*64
    const int o4 = (q & 63) * 4;
    const int k  = (q >> 6) & 1023;
    const int u  = q >> 16;
    float4 v = *(const float4*)(Wout + ((size_t)u * N_ + k) * O_ + o4);
    uint2 hi, lo; split4(v, hi, lo);
    const size_t o = ((size_t)u * N_ + k) * O_ + o4;
    *(uint2*)(g_Ohi + o) = hi;
    *(uint2*)(g_Olo + o) = lo;
}

// ---------------------------------------------------------------------------
// Kernel 2: state GEMM (pure bf16 consumer). CTA 128x128, 8 warps (2m x 4n),
// K = 1280 in 80 chunks of 16. Epilogue writes fp32 out + bf16 hi/lo NS.
// ---------------------------------------------------------------------------
#define APITCH 48           // 16 bf16 + 8 pad
#define ASZ (128 * APITCH)  // 6144
#define SBPITCH 272         // 128 bf16 + 8 pad
#define SBSZ (16 * SBPITCH) // 4352

__global__ __launch_bounds__(256, 1)
void state_kernel(const float* __restrict__ state, const float* __restrict__ bias,
                  float* __restrict__ out_state)
{
    __shared__ __align__(16) char sm[2 * 2 * ASZ + 2 * 2 * SBSZ];
    const int tid = threadIdx.x, wid = tid >> 5, lane = tid & 31;
    const int u = blockIdx.y;
    const int mbase = blockIdx.x * 128;

    auto Aoff = [](int buf, int part) { return (buf * 2 + part) * ASZ; };
    auto Boff = [](int buf, int part) { return 2 * 2 * ASZ + (buf * 2 + part) * SBSZ; };

    const int arow = tid >> 1, ahalf = tid & 1;            // A copy mapping
    const int bk = tid >> 4, bn = tid & 15;                // B copy mapping
    const size_t abase = ((size_t)arow * U_ + u) * KTOT + ahalf * 8;
    const size_t bbase0 = ((size_t)u * KTOT) * N_ + mbase + bn * 8;

    auto ldA = [&](int kt, uint4& h, uint4& l) {
        const size_t g = abase + kt * 16;
        h = *(const uint4*)(g_Ahi + g);
        l = *(const uint4*)(g_Alo + g);
    };
    auto ldB = [&](int kt, uint4& h, uint4& l) {
        const size_t g = bbase0 + (size_t)(kt * 16 + bk) * N_;
        h = *(const uint4*)(g_Bhi + g);
        l = *(const uint4*)(g_Blo + g);
    };
    auto stA = [&](int buf, uint4 h, uint4 l) {
        *(uint4*)(sm + Aoff(buf, 0) + arow * APITCH + ahalf * 16) = h;
        *(uint4*)(sm + Aoff(buf, 1) + arow * APITCH + ahalf * 16) = l;
    };
    auto stB = [&](int buf, uint4 h, uint4 l) {
        *(uint4*)(sm + Boff(buf, 0) + bk * SBPITCH + bn * 16) = h;
        *(uint4*)(sm + Boff(buf, 1) + bk * SBPITCH + bn * 16) = l;
    };

    const uint32_t smb = smem_u32(sm);
    const int wm = wid >> 2, wn = wid & 3;
    const int amat = lane >> 3, arin = lane & 7;
    const uint32_t a_lane = (uint32_t)(((amat & 1) * 8 + arin) * APITCH + (amat >> 1) * 16);
    const uint32_t b_lane = (uint32_t)((lane & 15) * SBPITCH);

    float acc[4][4][4];
#pragma unroll
    for (int t = 0; t < 4; ++t)
#pragma unroll
        for (int j = 0; j < 4; ++j)
#pragma unroll
            for (int r = 0; r < 4; ++r) acc[t][j][r] = 0.f;

    {
        uint4 ah, al, bh, bl;
        ldA(0, ah, al); ldB(0, bh, bl);
        stA(0, ah, al); stB(0, bh, bl);
    }
    __syncthreads();

    const int NT = 80;
    uint4 aHp, aLp, bHp, bLp;
    for (int kt = 0; kt < NT; ++kt) {
        const int cur = kt & 1;
        if (kt + 1 < NT) { ldA(kt + 1, aHp, aLp); ldB(kt + 1, bHp, bLp); }
        uint32_t ah[4][4], al[4][4], bh[4][2], bl[4][2];
        const uint32_t Ah = smb + Aoff(cur, 0) + a_lane + wm * 64 * APITCH;
        const uint32_t Al = smb + Aoff(cur, 1) + a_lane + wm * 64 * APITCH;
#pragma unroll
        for (int t = 0; t < 4; ++t) {
            ldsm_x4(ah[t], Ah + t * 16 * APITCH);
            ldsm_x4(al[t], Al + t * 16 * APITCH);
        }
        const uint32_t Bh = smb + Boff(cur, 0) + b_lane + wn * 64;
        const uint32_t Bl = smb + Boff(cur, 1) + b_lane + wn * 64;
#pragma unroll
        for (int j = 0; j < 4; ++j) {
            ldsm_x2t(bh[j], Bh + j * 16);
            ldsm_x2t(bl[j], Bl + j * 16);
        }
#pragma unroll
        for (int t = 0; t < 4; ++t)
#pragma unroll
            for (int j = 0; j < 4; ++j) {
                mma_bf16(acc[t][j], ah[t], bh[j]);
                mma_bf16(acc[t][j], ah[t], bl[j]);
                mma_bf16(acc[t][j], al[t], bh[j]);
            }
        if (kt + 1 < NT) {
            const int nxt = cur ^ 1;
            stA(nxt, aHp, aLp); stB(nxt, bHp, bLp);
        }
        __syncthreads();
    }

    // epilogue: bias + tanh + lr blend; write fp32 + bf16 hi/lo
    const int grp = lane >> 2, tig = lane & 3;
#pragma unroll
    for (int t = 0; t < 4; ++t) {
#pragma unroll
        for (int half = 0; half < 2; ++half) {
            const int b = wm * 64 + t * 16 + grp + half * 8;
            const float lrv = g_lr[b * U_ + u];
            const size_t rowoff = ((size_t)b * U_ + u) * N_;
#pragma unroll
            for (int j = 0; j < 4; ++j) {
                const int c = mbase + wn * 32 + j * 8 + tig * 2;
                const float p0 = acc[t][j][half * 2 + 0] + bias[u * N_ + c];
                const float p1 = acc[t][j][half * 2 + 1] + bias[u * N_ + c + 1];
                float2 o;
                o.x = (1.f - lrv) * state[rowoff + c]     + lrv * tanhf(p0);
                o.y = (1.f - lrv) * state[rowoff + c + 1] + lrv * tanhf(p1);
                *(float2*)(out_state + rowoff + c) = o;
                __nv_bfloat16 h0 = __float2bfloat16(o.x), h1 = __float2bfloat16(o.y);
                __nv_bfloat16 l0 = __float2bfloat16(o.x - __bfloat162float(h0));
                __nv_bfloat16 l1 = __float2bfloat16(o.y - __bfloat162float(h1));
                *(uint32_t*)(g_NShi + rowoff + c) =
                    (uint32_t)__bfloat16_as_ushort(h0) | ((uint32_t)__bfloat16_as_ushort(h1) << 16);
                *(uint32_t*)(g_NSlo + rowoff + c) =
                    (uint32_t)__bfloat16_as_ushort(l0) | ((uint32_t)__bfloat16_as_ushort(l1) << 16);
            }
        }
    }
}

// ---------------------------------------------------------------------------
// Kernel 3: out GEMM. CTA 64(batch) x 64(o), grid (4, 2, 16) = 128 CTAs.
// 8 warps (4m x 2n), warp tile 16x32. K=1024 in 64 chunks of 16.
// ---------------------------------------------------------------------------
#define OASZ (64 * APITCH)   // 3072
#define OBPITCH 144          // 64 bf16 + 8 pad
#define OBSZ (16 * OBPITCH)  // 2304

__global__ __launch_bounds__(256, 2)
void out_kernel(float* __restrict__ outy)
{
    __shared__ __align__(16) char sm[2 * 2 * OASZ + 2 * 2 * OBSZ];
    const int tid = threadIdx.x, wid = tid >> 5, lane = tid & 31;
    const int u = blockIdx.z;
    const int btile = blockIdx.y * 64;
    const int obase = blockIdx.x * 64;

    auto Aoff = [](int buf, int part) { return (buf * 2 + part) * OASZ; };
    auto Boff = [](int buf, int part) { return 2 * 2 * OASZ + (buf * 2 + part) * OBSZ; };

    const int arow = tid >> 2, aq = tid & 3;
    const int bk = tid >> 4, bn = tid & 15;
    const size_t abase = ((size_t)(btile + arow) * U_ + u) * N_ + aq * 4;
    const size_t bbase0 = ((size_t)u * N_) * O_ + obase + bn * 4;

    auto ldA = [&](int kt, uint2& h, uint2& l) {
        const size_t g = abase + kt * 16;
        h = *(const uint2*)(g_NShi + g);
        l = *(const uint2*)(g_NSlo + g);
    };
    auto ldB = [&](int kt, uint2& h, uint2& l) {
        const size_t g = bbase0 + (size_t)(kt * 16 + bk) * O_;
        h = *(const uint2*)(g_Ohi + g);
        l = *(const uint2*)(g_Olo + g);
    };
    auto stA = [&](int buf, uint2 h, uint2 l) {
        *(uint2*)(sm + Aoff(buf, 0) + arow * APITCH + aq * 8) = h;
        *(uint2*)(sm + Aoff(buf, 1) + arow * APITCH + aq * 8) = l;
    };
    auto stB = [&](int buf, uint2 h, uint2 l) {
        *(uint2*)(sm + Boff(buf, 0) + bk * OBPITCH + bn * 8) = h;
        *(uint2*)(sm + Boff(buf, 1) + bk * OBPITCH + bn * 8) = l;
    };

    const uint32_t smb = smem_u32(sm);
    const int wm = wid >> 1, wn = wid & 1;
    const int amat = lane >> 3, arin = lane & 7;
    const uint32_t a_lane = (uint32_t)(((amat & 1) * 8 + arin) * APITCH + (amat >> 1) * 16);
    const uint32_t b_lane = (uint32_t)((lane & 15) * OBPITCH);

    float acc[4][4];
#pragma unroll
    for (int j = 0; j < 4; ++j)
#pragma unroll
        for (int r = 0; r < 4; ++r) acc[j][r] = 0.f;

    {
        uint2 ah, al, bh, bl;
        ldA(0, ah, al); ldB(0, bh, bl);
        stA(0, ah, al); stB(0, bh, bl);
    }
    __syncthreads();

    const int NT = 64;
    uint2 aHp, aLp, bHp, bLp;
    for (int kt = 0; kt < NT; ++kt) {
        const int cur = kt & 1;
        if (kt + 1 < NT) { ldA(kt + 1, aHp, aLp); ldB(kt + 1, bHp, bLp); }
        uint32_t ah[4], al[4], bh[4][2], bl[4][2];
        const uint32_t Ah = smb + Aoff(cur, 0) + a_lane + wm * 16 * APITCH;
        const uint32_t Al = smb + Aoff(cur, 1) + a_lane + wm * 16 * APITCH;
        ldsm_x4(ah, Ah);
        ldsm_x4(al, Al);
        const uint32_t Bh = smb + Boff(cur, 0) + b_lane + wn * 64;
        const uint32_t Bl = smb + Boff(cur, 1) + b_lane + wn * 64;
#pragma unroll
        for (int j = 0; j < 4; ++j) {
            ldsm_x2t(bh[j], Bh + j * 16);
            ldsm_x2t(bl[j], Bl + j * 16);
        }
#pragma unroll
        for (int j = 0; j < 4; ++j) {
            mma_bf16(acc[j], ah, bh[j]);
            mma_bf16(acc[j], ah, bl[j]);
            mma_bf16(acc[j], al, bh[j]);
        }
        if (kt + 1 < NT) {
            const int nxt = cur ^ 1;
            stA(nxt, aHp, aLp); stB(nxt, bHp, bLp);
        }
        __syncthreads();
    }

    const int grp = lane >> 2, tig = lane & 3;
#pragma unroll
    for (int half = 0; half < 2; ++half) {
        const int b = btile + wm * 16 + grp + half * 8;
        float* orow = outy + ((size_t)b * U_ + u) * O_;
#pragma unroll
        for (int j = 0; j < 4; ++j) {
            const int c = obase + wn * 32 + j * 8 + tig * 2;
            float2 o;
            o.x = acc[j][half * 2 + 0];
            o.y = acc[j][half * 2 + 1];
            *(float2*)(orow + c) = o;
        }
    }
}

// ---------------------------------------------------------------------------
extern "C" void kernel_launch(void* const* d_in, const int* in_sizes, int n_in,
                              void* d_out, int out_size)
{
    const float* X    = (const float*)d_in[0];
    const float* st   = (const float*)d_in[1];
    const float* W    = (const float*)d_in[2];
    const float* Win  = (const float*)d_in[3];
    const float* bias = (const float*)d_in[4];
    const float* Wout = (const float*)d_in[5];
    const float* sr   = (const float*)d_in[6];
    const float* alr  = (const float*)d_in[7];
    const float* temp = (const float*)d_in[8];

    float* out_state = (float*)d_out;                     // [B,U,N]
    float* out_y     = out_state + (size_t)B_ * U_ * N_;  // [B,U,O]

    lr_kernel<<<B_, 512>>>(X, alr, temp);
    convA_kernel<<<(B_ * U_ * (KTOT / 4)) / 256, 256>>>(X, st);
    convO_kernel<<<(U_ * N_ * (O_ / 4)) / 256, 256>>>(Wout);
    convB_kernel<<<(U_ * KTOT * (N_ / 4)) / 256, 256>>>(W, Win, sr);
    state_kernel<<<dim3(N_ / 128, U_), 256>>>(st, bias, out_state);
    out_kernel<<<dim3(O_ / 64, B_ / 64, U_), 256>>>(out_y);
}